// round 13
// baseline (speedup 1.0000x reference)
#include <cuda_runtime.h>

#define Nn 50000
#define Rr 16
#define Hh 32
#define Ll 8
#define Ee 1600000
#define TNODES 256

// Scratch (static __device__ arrays: allocation-free per harness rules)
__device__ __align__(16) int   g_cnt[Rr * Nn];       // per-(relation,dst) edge counts
__device__ __align__(16) float g_enorm[Ee];          // per-edge 1/deg_r(dst) (layer1 writes)
__device__ __align__(16) float g_h1[Nn * Hh];        // layer-1 aggregation
__device__ __align__(16) float g_T[Nn * Rr * Ll];    // T[n][r][l] = (h1[n,:] @ W2[r])[l]

// Vector reduction: 4x fp32 add in one L2 atomic op (sm_90+)
__device__ __forceinline__ void red_add_v4(float* p, float4 v) {
    asm volatile("red.global.add.v4.f32 [%0], {%1,%2,%3,%4};"
                 :: "l"(p), "f"(v.x), "f"(v.y), "f"(v.z), "f"(v.w)
                 : "memory");
}

// ---------------------------------------------------------------------------
// Zero accumulators (g_cnt, g_h1). out is initialized by k_T.
// ---------------------------------------------------------------------------
__global__ void k_zero() {
    int i = blockIdx.x * blockDim.x + threadIdx.x;
    int stride = gridDim.x * blockDim.x;
    float4 z = make_float4(0.f, 0.f, 0.f, 0.f);
    int4* c4 = (int4*)g_cnt;
    float4* h4 = (float4*)g_h1;
    for (int j = i; j < (Rr * Nn) / 4; j += stride) c4[j] = make_int4(0, 0, 0, 0);
    for (int j = i; j < (Nn * Hh) / 4; j += stride) h4[j] = z;
}

// ---------------------------------------------------------------------------
// Per-(relation,dst) edge counts. 8 edges per thread (MLP=8).
// ---------------------------------------------------------------------------
__global__ void k_count(const int* __restrict__ et, const int* __restrict__ dst) {
    int t = blockIdx.x * blockDim.x + threadIdx.x;
    if (t >= Ee / 8) return;
    int e0 = t * 8;
    int4 da = *(const int4*)(dst + e0);
    int4 db = *(const int4*)(dst + e0 + 4);
    int4 ra = *(const int4*)(et + e0);
    int4 rb = *(const int4*)(et + e0 + 4);
    atomicAdd(&g_cnt[ra.x * Nn + da.x], 1);
    atomicAdd(&g_cnt[ra.y * Nn + da.y], 1);
    atomicAdd(&g_cnt[ra.z * Nn + da.z], 1);
    atomicAdd(&g_cnt[ra.w * Nn + da.w], 1);
    atomicAdd(&g_cnt[rb.x * Nn + db.x], 1);
    atomicAdd(&g_cnt[rb.y * Nn + db.y], 1);
    atomicAdd(&g_cnt[rb.z * Nn + db.z], 1);
    atomicAdd(&g_cnt[rb.w * Nn + db.w], 1);
}

// ---------------------------------------------------------------------------
// Layer 1: 8 threads per edge (quarter-row each), 4 edges per thread.
//   norm = 1/max(cnt[r*N+d],1)   (inline gather)
//   g_h1[dst, q*4..] += W1[r, src, q*4..] * norm
// Lane q==0 stores the 4 edge-norms to g_enorm for layer2 reuse.
// ---------------------------------------------------------------------------
__global__ void k_layer1(const int* __restrict__ src, const int* __restrict__ dst,
                         const int* __restrict__ et, const float* __restrict__ W1) {
    int g = blockIdx.x * blockDim.x + threadIdx.x;
    int grp = g >> 3;        // which edge-quad
    int q = g & 7;           // which quarter of the 32-wide row
    if (grp >= Ee / 4) return;
    int e0 = grp * 4;

    int4 s4 = *(const int4*)(src + e0);
    int4 d4 = *(const int4*)(dst + e0);
    int4 r4 = *(const int4*)(et + e0);
    int ss[4] = {s4.x, s4.y, s4.z, s4.w};
    int dd[4] = {d4.x, d4.y, d4.z, d4.w};
    int rr[4] = {r4.x, r4.y, r4.z, r4.w};

    float  nn[4];
    float4 ww[4];
#pragma unroll
    for (int k = 0; k < 4; k++) {
        nn[k] = 1.0f / fmaxf((float)__ldg(&g_cnt[rr[k] * Nn + dd[k]]), 1.0f);
        ww[k] = *(const float4*)(W1 + (rr[k] * Nn + ss[k]) * Hh + q * 4);
    }
    if (q == 0) {
        *(float4*)(g_enorm + e0) = make_float4(nn[0], nn[1], nn[2], nn[3]);
    }
#pragma unroll
    for (int k = 0; k < 4; k++) {
        float4 v = make_float4(ww[k].x * nn[k], ww[k].y * nn[k],
                               ww[k].z * nn[k], ww[k].w * nn[k]);
        red_add_v4(&g_h1[dd[k] * Hh + q * 4], v);
    }
}

// ---------------------------------------------------------------------------
// Fused k_T (register-weight GEMM, 256-node tiles):
//   h = relu(agg + root1 + b1)                (staged: 32KB shared per tile)
//   T[n][r][l] = sum_h h[n,h] * W2[r,h,l]     (w column = 32 regs, from shared)
//   out[n,l]   = (h @ root2)[l] + b2[l]       (base for layer2 REDs)
// Block = 512 thr. W2 staged ONCE per block (coalesced 16KB copy), amortized
// over 256 nodes -> kills the per-tile strided W2 reload that bound R10-R12.
// Per node per thread: 8 broadcast LDS.128 + 32 FFMA + 1 coalesced STG.32.
// ---------------------------------------------------------------------------
__global__ void __launch_bounds__(512, 2)
k_T(const float* __restrict__ W2, const float* __restrict__ root1,
    const float* __restrict__ b1, const float* __restrict__ root2,
    const float* __restrict__ b2, float* __restrict__ out) {
    __shared__ float4 sH[TNODES * 8];    // 256 nodes x 32 h = 32KB
    __shared__ float  sW2[Rr * Hh * Ll]; // 16KB
    __shared__ float  sR[Hh * Ll];       // 1KB

    int tid = threadIdx.x;
    int tile = blockIdx.x;

    for (int i = tid; i < Rr * Hh * Ll; i += 512) sW2[i] = W2[i];
    for (int i = tid; i < Hh * Ll; i += 512) sR[i] = root2[i];

    // Stage relu(agg + root1 + b1) for 256 nodes (coalesced float4 loads)
    int base4 = tile * (TNODES * 8);     // float4 index into [n][h] arrays
#pragma unroll
    for (int k = 0; k < 4; k++) {
        int idx4 = tid + k * 512;        // 0..2047
        int g4 = base4 + idx4;
        float4 hv = make_float4(0.f, 0.f, 0.f, 0.f);
        if (g4 < (Nn * Hh) / 4) {
            float4 av = ((const float4*)g_h1)[g4];
            float4 rv = ((const float4*)root1)[g4];
            int h0 = (idx4 & 7) * 4;
            hv.x = fmaxf(av.x + rv.x + __ldg(b1 + h0 + 0), 0.0f);
            hv.y = fmaxf(av.y + rv.y + __ldg(b1 + h0 + 1), 0.0f);
            hv.z = fmaxf(av.z + rv.z + __ldg(b1 + h0 + 2), 0.0f);
            hv.w = fmaxf(av.w + rv.w + __ldg(b1 + h0 + 3), 0.0f);
        }
        sH[idx4] = hv;
    }
    __syncthreads();

    // W2 column into registers: thread owns (r, l); conflict-free LDS
    int rl = tid & 127;                  // r*8 + l
    int r  = rl >> 3;
    int l  = rl & 7;
    int grp = tid >> 7;                  // 4 node-groups of 64 nodes
    float w[Hh];
#pragma unroll
    for (int hh = 0; hh < Hh; hh++)
        w[hh] = sW2[(r * Hh + hh) * Ll + l];

    // Out-base: 2048 (node,l) tasks over 512 threads
#pragma unroll
    for (int k = 0; k < 4; k++) {
        int task = tid + k * 512;
        int node = task >> 3;
        int lo = task & 7;
        int n = tile * TNODES + node;
        if (n < Nn) {
            const float* sHf = (const float*)sH;
            float y = __ldg(b2 + lo);
#pragma unroll
            for (int hh = 0; hh < Hh; hh++)
                y += sHf[node * Hh + hh] * sR[hh * Ll + lo];
            out[n * Ll + lo] = y;
        }
    }

    // Main: each (grp, r, l) thread handles 64 nodes
#pragma unroll 8
    for (int i = 0; i < 64; i++) {
        int ni = grp * 64 + i;
        int n = tile * TNODES + ni;
        if (n >= Nn) break;
        float a0 = 0.0f, a1 = 0.0f, a2 = 0.0f, a3 = 0.0f;
#pragma unroll
        for (int j = 0; j < 8; j++) {
            float4 h4 = sH[ni * 8 + j];          // broadcast LDS.128
            a0 += h4.x * w[j * 4 + 0];
            a1 += h4.y * w[j * 4 + 1];
            a2 += h4.z * w[j * 4 + 2];
            a3 += h4.w * w[j * 4 + 3];
        }
        g_T[n * (Rr * Ll) + rl] = (a0 + a1) + (a2 + a3);
    }
}

// ---------------------------------------------------------------------------
// Layer 2 edge pass: 2 threads per edge (half-row each), 8 edges per thread.
//   out[dst, half*4..] += enorm[e] * T[src][r][half*4..]
// ---------------------------------------------------------------------------
__global__ void k_layer2(const int* __restrict__ src, const int* __restrict__ dst,
                         const int* __restrict__ et, float* __restrict__ out) {
    int g = blockIdx.x * blockDim.x + threadIdx.x;
    int oct = g >> 1;
    int half = g & 1;
    if (oct >= Ee / 8) return;
    int e0 = oct * 8;

    int4 sa = *(const int4*)(src + e0);
    int4 sb = *(const int4*)(src + e0 + 4);
    int4 da = *(const int4*)(dst + e0);
    int4 db = *(const int4*)(dst + e0 + 4);
    int4 ra = *(const int4*)(et + e0);
    int4 rb = *(const int4*)(et + e0 + 4);
    float4 na = *(const float4*)(g_enorm + e0);
    float4 nb = *(const float4*)(g_enorm + e0 + 4);
    int ss[8] = {sa.x, sa.y, sa.z, sa.w, sb.x, sb.y, sb.z, sb.w};
    int dd[8] = {da.x, da.y, da.z, da.w, db.x, db.y, db.z, db.w};
    int rr[8] = {ra.x, ra.y, ra.z, ra.w, rb.x, rb.y, rb.z, rb.w};
    float nn[8] = {na.x, na.y, na.z, na.w, nb.x, nb.y, nb.z, nb.w};

    float4 tv[8];
#pragma unroll
    for (int k = 0; k < 8; k++) {
        tv[k] = *(const float4*)(g_T + (ss[k] * Rr + rr[k]) * Ll + half * 4);
    }
#pragma unroll
    for (int k = 0; k < 8; k++) {
        float4 v = make_float4(tv[k].x * nn[k], tv[k].y * nn[k],
                               tv[k].z * nn[k], tv[k].w * nn[k]);
        red_add_v4(&out[dd[k] * Ll + half * 4], v);
    }
}

// ---------------------------------------------------------------------------
// Final: out = sigmoid(out), elementwise
// ---------------------------------------------------------------------------
__global__ void k_final(float* __restrict__ out) {
    int i = blockIdx.x * blockDim.x + threadIdx.x;
    if (i >= (Nn * Ll) / 4) return;
    float4 v = ((const float4*)out)[i];
    v.x = 1.0f / (1.0f + expf(-v.x));
    v.y = 1.0f / (1.0f + expf(-v.y));
    v.z = 1.0f / (1.0f + expf(-v.z));
    v.w = 1.0f / (1.0f + expf(-v.w));
    ((float4*)out)[i] = v;
}

// ---------------------------------------------------------------------------
extern "C" void kernel_launch(void* const* d_in, const int* in_sizes, int n_in,
                              void* d_out, int out_size) {
    const int* ei    = (const int*)d_in[0];    // edge_index [2, E]
    const int* et    = (const int*)d_in[1];    // edge_type  [E]
    const float* W1  = (const float*)d_in[2];  // [R, N, H]
    const float* rt1 = (const float*)d_in[3];  // [N, H]
    const float* b1  = (const float*)d_in[4];  // [H]
    const float* W2  = (const float*)d_in[5];  // [R, H, L]
    const float* rt2 = (const float*)d_in[6];  // [H, L]
    const float* b2  = (const float*)d_in[7];  // [L]
    float* out = (float*)d_out;                // [N, L]

    const int* src = ei;
    const int* dst = ei + Ee;

    k_zero<<<1024, 256>>>();
    k_count<<<(Ee / 8 + 255) / 256, 256>>>(et, dst);
    k_layer1<<<(Ee / 4) * 8 / 256, 256>>>(src, dst, et, W1);     // 8 thr/edge, 4 edges/thr
    k_T<<<(Nn + TNODES - 1) / TNODES, 512>>>(W2, rt1, b1, rt2, b2, out);
    k_layer2<<<((Ee / 8) * 2 + 255) / 256, 256>>>(src, dst, et, out); // 2 thr/edge, 8 edges/thr
    k_final<<<((Nn * Ll) / 4 + 255) / 256, 256>>>(out);
}

// round 14
// speedup vs baseline: 1.0487x; 1.0487x over previous
#include <cuda_runtime.h>

#define Nn 50000
#define Rr 16
#define Hh 32
#define Ll 8
#define Ee 1600000
#define KT_BLOCKS 296
#define NT 169            // nodes per k_T block: 296*169 = 50024 >= Nn

// Scratch (static __device__ arrays: allocation-free per harness rules)
__device__ __align__(16) int   g_cnt[Rr * Nn];       // per-(relation,dst) edge counts
__device__ __align__(16) float g_enorm[Ee];          // per-edge 1/deg_r(dst) (layer1 writes)
__device__ __align__(16) float g_h1[Nn * Hh];        // layer-1 aggregation
__device__ __align__(16) float g_T[Nn * Rr * Ll];    // T[n][r][l] = (h1[n,:] @ W2[r])[l]

// Vector reduction: 4x fp32 add in one L2 atomic op (sm_90+)
__device__ __forceinline__ void red_add_v4(float* p, float4 v) {
    asm volatile("red.global.add.v4.f32 [%0], {%1,%2,%3,%4};"
                 :: "l"(p), "f"(v.x), "f"(v.y), "f"(v.z), "f"(v.w)
                 : "memory");
}

// ---------------------------------------------------------------------------
// Zero accumulators (g_cnt, g_h1). out is initialized by k_T.
// ---------------------------------------------------------------------------
__global__ void k_zero() {
    int i = blockIdx.x * blockDim.x + threadIdx.x;
    int stride = gridDim.x * blockDim.x;
    float4 z = make_float4(0.f, 0.f, 0.f, 0.f);
    int4* c4 = (int4*)g_cnt;
    float4* h4 = (float4*)g_h1;
    for (int j = i; j < (Rr * Nn) / 4; j += stride) c4[j] = make_int4(0, 0, 0, 0);
    for (int j = i; j < (Nn * Hh) / 4; j += stride) h4[j] = z;
}

// ---------------------------------------------------------------------------
// Per-(relation,dst) edge counts. 8 edges per thread (MLP=8).
// ---------------------------------------------------------------------------
__global__ void k_count(const int* __restrict__ et, const int* __restrict__ dst) {
    int t = blockIdx.x * blockDim.x + threadIdx.x;
    if (t >= Ee / 8) return;
    int e0 = t * 8;
    int4 da = *(const int4*)(dst + e0);
    int4 db = *(const int4*)(dst + e0 + 4);
    int4 ra = *(const int4*)(et + e0);
    int4 rb = *(const int4*)(et + e0 + 4);
    atomicAdd(&g_cnt[ra.x * Nn + da.x], 1);
    atomicAdd(&g_cnt[ra.y * Nn + da.y], 1);
    atomicAdd(&g_cnt[ra.z * Nn + da.z], 1);
    atomicAdd(&g_cnt[ra.w * Nn + da.w], 1);
    atomicAdd(&g_cnt[rb.x * Nn + db.x], 1);
    atomicAdd(&g_cnt[rb.y * Nn + db.y], 1);
    atomicAdd(&g_cnt[rb.z * Nn + db.z], 1);
    atomicAdd(&g_cnt[rb.w * Nn + db.w], 1);
}

// ---------------------------------------------------------------------------
// Layer 1: 8 threads per edge (quarter-row each), 4 edges per thread.
//   norm = 1/max(cnt[r*N+d],1)   (inline gather)
//   g_h1[dst, q*4..] += W1[r, src, q*4..] * norm
// Lane q==0 stores the 4 edge-norms to g_enorm for layer2 reuse.
// ---------------------------------------------------------------------------
__global__ void k_layer1(const int* __restrict__ src, const int* __restrict__ dst,
                         const int* __restrict__ et, const float* __restrict__ W1) {
    int g = blockIdx.x * blockDim.x + threadIdx.x;
    int grp = g >> 3;        // which edge-quad
    int q = g & 7;           // which quarter of the 32-wide row
    if (grp >= Ee / 4) return;
    int e0 = grp * 4;

    int4 s4 = *(const int4*)(src + e0);
    int4 d4 = *(const int4*)(dst + e0);
    int4 r4 = *(const int4*)(et + e0);
    int ss[4] = {s4.x, s4.y, s4.z, s4.w};
    int dd[4] = {d4.x, d4.y, d4.z, d4.w};
    int rr[4] = {r4.x, r4.y, r4.z, r4.w};

    float  nn[4];
    float4 ww[4];
#pragma unroll
    for (int k = 0; k < 4; k++) {
        nn[k] = 1.0f / fmaxf((float)__ldg(&g_cnt[rr[k] * Nn + dd[k]]), 1.0f);
        ww[k] = *(const float4*)(W1 + (rr[k] * Nn + ss[k]) * Hh + q * 4);
    }
    if (q == 0) {
        *(float4*)(g_enorm + e0) = make_float4(nn[0], nn[1], nn[2], nn[3]);
    }
#pragma unroll
    for (int k = 0; k < 4; k++) {
        float4 v = make_float4(ww[k].x * nn[k], ww[k].y * nn[k],
                               ww[k].z * nn[k], ww[k].w * nn[k]);
        red_add_v4(&g_h1[dd[k] * Hh + q * 4], v);
    }
}

// ---------------------------------------------------------------------------
// Fused k_T (register-weight GEMM, single balanced wave):
//   h = relu(agg + root1 + b1)                (staged ~21.6KB shared per block)
//   T[n][r][l] = sum_h h[n,h] * W2[r,h,l]     (w column = 32 regs, via shared)
//   out[n,l]   = (h @ root2)[l] + b2[l]       (base for layer2 REDs)
// Grid = 296 = 2 blocks x 148 SMs, each block owns 169 contiguous nodes:
// exactly ONE wave, no quantization tail (R13's 1.32x stretch).
// ---------------------------------------------------------------------------
__global__ void __launch_bounds__(512, 2)
k_T(const float* __restrict__ W2, const float* __restrict__ root1,
    const float* __restrict__ b1, const float* __restrict__ root2,
    const float* __restrict__ b2, float* __restrict__ out) {
    __shared__ float4 sH[NT * 8];        // 169 nodes x 32 h = 21.6KB
    __shared__ float  sW2[Rr * Hh * Ll]; // 16KB
    __shared__ float  sR[Hh * Ll];       // 1KB

    int tid = threadIdx.x;
    int n0 = blockIdx.x * NT;            // first node of this block

    for (int i = tid; i < Rr * Hh * Ll; i += 512) sW2[i] = W2[i];
    for (int i = tid; i < Hh * Ll; i += 512) sR[i] = root2[i];

    // Stage relu(agg + root1 + b1) for NT nodes (coalesced float4 loads)
    int base4 = n0 * 8;                  // float4 index into [n][h] arrays
    for (int idx4 = tid; idx4 < NT * 8; idx4 += 512) {
        int g4 = base4 + idx4;
        float4 hv = make_float4(0.f, 0.f, 0.f, 0.f);
        if (g4 < (Nn * Hh) / 4) {
            float4 av = ((const float4*)g_h1)[g4];
            float4 rv = ((const float4*)root1)[g4];
            int h0 = (idx4 & 7) * 4;
            hv.x = fmaxf(av.x + rv.x + __ldg(b1 + h0 + 0), 0.0f);
            hv.y = fmaxf(av.y + rv.y + __ldg(b1 + h0 + 1), 0.0f);
            hv.z = fmaxf(av.z + rv.z + __ldg(b1 + h0 + 2), 0.0f);
            hv.w = fmaxf(av.w + rv.w + __ldg(b1 + h0 + 3), 0.0f);
        }
        sH[idx4] = hv;
    }
    __syncthreads();

    // W2 column into registers: thread owns (r, l); conflict-free LDS
    int rl = tid & 127;                  // r*8 + l
    int r  = rl >> 3;
    int l  = rl & 7;
    int grp = tid >> 7;                  // 4 node-groups
    float w[Hh];
#pragma unroll
    for (int hh = 0; hh < Hh; hh++)
        w[hh] = sW2[(r * Hh + hh) * Ll + l];

    // Out-base: NT*8 (node,l) tasks over 512 threads
    for (int task = tid; task < NT * 8; task += 512) {
        int node = task >> 3;
        int lo = task & 7;
        int n = n0 + node;
        if (n < Nn) {
            const float* sHf = (const float*)sH;
            float y = __ldg(b2 + lo);
#pragma unroll
            for (int hh = 0; hh < Hh; hh++)
                y += sHf[node * Hh + hh] * sR[hh * Ll + lo];
            out[n * Ll + lo] = y;
        }
    }

    // Main: group grp handles nodes ni = grp, grp+4, ... (43 per group)
#pragma unroll 4
    for (int i = 0; i < 43; i++) {
        int ni = grp + i * 4;
        if (ni >= NT) break;
        int n = n0 + ni;
        if (n >= Nn) break;
        float a0 = 0.0f, a1 = 0.0f, a2 = 0.0f, a3 = 0.0f;
#pragma unroll
        for (int j = 0; j < 8; j++) {
            float4 h4 = sH[ni * 8 + j];          // broadcast LDS.128
            a0 += h4.x * w[j * 4 + 0];
            a1 += h4.y * w[j * 4 + 1];
            a2 += h4.z * w[j * 4 + 2];
            a3 += h4.w * w[j * 4 + 3];
        }
        g_T[n * (Rr * Ll) + rl] = (a0 + a1) + (a2 + a3);
    }
}

// ---------------------------------------------------------------------------
// Layer 2 edge pass: 2 threads per edge (half-row each), 8 edges per thread.
//   out[dst, half*4..] += enorm[e] * T[src][r][half*4..]
// ---------------------------------------------------------------------------
__global__ void k_layer2(const int* __restrict__ src, const int* __restrict__ dst,
                         const int* __restrict__ et, float* __restrict__ out) {
    int g = blockIdx.x * blockDim.x + threadIdx.x;
    int oct = g >> 1;
    int half = g & 1;
    if (oct >= Ee / 8) return;
    int e0 = oct * 8;

    int4 sa = *(const int4*)(src + e0);
    int4 sb = *(const int4*)(src + e0 + 4);
    int4 da = *(const int4*)(dst + e0);
    int4 db = *(const int4*)(dst + e0 + 4);
    int4 ra = *(const int4*)(et + e0);
    int4 rb = *(const int4*)(et + e0 + 4);
    float4 na = *(const float4*)(g_enorm + e0);
    float4 nb = *(const float4*)(g_enorm + e0 + 4);
    int ss[8] = {sa.x, sa.y, sa.z, sa.w, sb.x, sb.y, sb.z, sb.w};
    int dd[8] = {da.x, da.y, da.z, da.w, db.x, db.y, db.z, db.w};
    int rr[8] = {ra.x, ra.y, ra.z, ra.w, rb.x, rb.y, rb.z, rb.w};
    float nn[8] = {na.x, na.y, na.z, na.w, nb.x, nb.y, nb.z, nb.w};

    float4 tv[8];
#pragma unroll
    for (int k = 0; k < 8; k++) {
        tv[k] = *(const float4*)(g_T + (ss[k] * Rr + rr[k]) * Ll + half * 4);
    }
#pragma unroll
    for (int k = 0; k < 8; k++) {
        float4 v = make_float4(tv[k].x * nn[k], tv[k].y * nn[k],
                               tv[k].z * nn[k], tv[k].w * nn[k]);
        red_add_v4(&out[dd[k] * Ll + half * 4], v);
    }
}

// ---------------------------------------------------------------------------
// Final: out = sigmoid(out), elementwise (MUFU exp)
// ---------------------------------------------------------------------------
__global__ void k_final(float* __restrict__ out) {
    int i = blockIdx.x * blockDim.x + threadIdx.x;
    if (i >= (Nn * Ll) / 4) return;
    float4 v = ((const float4*)out)[i];
    v.x = 1.0f / (1.0f + __expf(-v.x));
    v.y = 1.0f / (1.0f + __expf(-v.y));
    v.z = 1.0f / (1.0f + __expf(-v.z));
    v.w = 1.0f / (1.0f + __expf(-v.w));
    ((float4*)out)[i] = v;
}

// ---------------------------------------------------------------------------
extern "C" void kernel_launch(void* const* d_in, const int* in_sizes, int n_in,
                              void* d_out, int out_size) {
    const int* ei    = (const int*)d_in[0];    // edge_index [2, E]
    const int* et    = (const int*)d_in[1];    // edge_type  [E]
    const float* W1  = (const float*)d_in[2];  // [R, N, H]
    const float* rt1 = (const float*)d_in[3];  // [N, H]
    const float* b1  = (const float*)d_in[4];  // [H]
    const float* W2  = (const float*)d_in[5];  // [R, H, L]
    const float* rt2 = (const float*)d_in[6];  // [H, L]
    const float* b2  = (const float*)d_in[7];  // [L]
    float* out = (float*)d_out;                // [N, L]

    const int* src = ei;
    const int* dst = ei + Ee;

    k_zero<<<1024, 256>>>();
    k_count<<<(Ee / 8 + 255) / 256, 256>>>(et, dst);
    k_layer1<<<(Ee / 4) * 8 / 256, 256>>>(src, dst, et, W1);     // 8 thr/edge, 4 edges/thr
    k_T<<<KT_BLOCKS, 512>>>(W2, rt1, b1, rt2, b2, out);          // 1 balanced wave
    k_layer2<<<((Ee / 8) * 2 + 255) / 256, 256>>>(src, dst, et, out); // 2 thr/edge, 8 edges/thr
    k_final<<<((Nn * Ll) / 4 + 255) / 256, 256>>>(out);
}

// round 15
// speedup vs baseline: 1.1663x; 1.1121x over previous
#include <cuda_runtime.h>

#define Nn 50000
#define Rr 16
#define Hh 32
#define Ll 8
#define Ee 1600000
#define KT_BLOCKS 296
#define NT 169            // nodes per k_T block: 296*169 = 50024 >= Nn

// Scratch (static __device__ arrays: allocation-free per harness rules)
__device__ __align__(16) int   g_cnt[Rr * Nn];       // per-(relation,dst) edge counts
__device__ __align__(16) float g_enorm[Ee];          // per-edge 1/deg_r(dst) (layer1 writes)
__device__ __align__(16) float g_h1[Nn * Hh];        // layer-1 aggregation
__device__ __align__(16) float g_T[Nn * Rr * Ll];    // T[n][r][l] = (h1[n,:] @ W2[r])[l]

// Vector reduction: 4x fp32 add in one L2 atomic op (sm_90+)
__device__ __forceinline__ void red_add_v4(float* p, float4 v) {
    asm volatile("red.global.add.v4.f32 [%0], {%1,%2,%3,%4};"
                 :: "l"(p), "f"(v.x), "f"(v.y), "f"(v.z), "f"(v.w)
                 : "memory");
}

// ---------------------------------------------------------------------------
// Zero accumulators (g_cnt, g_h1). out is initialized by k_T.
// ---------------------------------------------------------------------------
__global__ void k_zero() {
    int i = blockIdx.x * blockDim.x + threadIdx.x;
    int stride = gridDim.x * blockDim.x;
    float4 z = make_float4(0.f, 0.f, 0.f, 0.f);
    int4* c4 = (int4*)g_cnt;
    float4* h4 = (float4*)g_h1;
    for (int j = i; j < (Rr * Nn) / 4; j += stride) c4[j] = make_int4(0, 0, 0, 0);
    for (int j = i; j < (Nn * Hh) / 4; j += stride) h4[j] = z;
}

// ---------------------------------------------------------------------------
// Per-(relation,dst) edge counts. 8 edges per thread (MLP=8).
// ---------------------------------------------------------------------------
__global__ void k_count(const int* __restrict__ et, const int* __restrict__ dst) {
    int t = blockIdx.x * blockDim.x + threadIdx.x;
    if (t >= Ee / 8) return;
    int e0 = t * 8;
    int4 da = *(const int4*)(dst + e0);
    int4 db = *(const int4*)(dst + e0 + 4);
    int4 ra = *(const int4*)(et + e0);
    int4 rb = *(const int4*)(et + e0 + 4);
    atomicAdd(&g_cnt[ra.x * Nn + da.x], 1);
    atomicAdd(&g_cnt[ra.y * Nn + da.y], 1);
    atomicAdd(&g_cnt[ra.z * Nn + da.z], 1);
    atomicAdd(&g_cnt[ra.w * Nn + da.w], 1);
    atomicAdd(&g_cnt[rb.x * Nn + db.x], 1);
    atomicAdd(&g_cnt[rb.y * Nn + db.y], 1);
    atomicAdd(&g_cnt[rb.z * Nn + db.z], 1);
    atomicAdd(&g_cnt[rb.w * Nn + db.w], 1);
}

// ---------------------------------------------------------------------------
// Layer 1: 8 threads per edge (quarter-row each), 8 edges per thread (MLP=8).
//   norm = 1/max(cnt[r*N+d],1)   (inline gather)
//   g_h1[dst, q*4..] += W1[r, src, q*4..] * norm
// Lane q==0 stores the 8 edge-norms to g_enorm for layer2 reuse.
// All 8 W1 LDG.128s are issued back-to-back -> 8 outstanding lines/thread.
// ---------------------------------------------------------------------------
__global__ void k_layer1(const int* __restrict__ src, const int* __restrict__ dst,
                         const int* __restrict__ et, const float* __restrict__ W1) {
    int g = blockIdx.x * blockDim.x + threadIdx.x;
    int grp = g >> 3;        // which edge-octet
    int q = g & 7;           // which quarter of the 32-wide row
    if (grp >= Ee / 8) return;
    int e0 = grp * 8;

    int4 sa = *(const int4*)(src + e0);
    int4 sb = *(const int4*)(src + e0 + 4);
    int4 d4a = *(const int4*)(dst + e0);
    int4 d4b = *(const int4*)(dst + e0 + 4);
    int4 r4a = *(const int4*)(et + e0);
    int4 r4b = *(const int4*)(et + e0 + 4);
    int ss[8] = {sa.x, sa.y, sa.z, sa.w, sb.x, sb.y, sb.z, sb.w};
    int dd[8] = {d4a.x, d4a.y, d4a.z, d4a.w, d4b.x, d4b.y, d4b.z, d4b.w};
    int rr[8] = {r4a.x, r4a.y, r4a.z, r4a.w, r4b.x, r4b.y, r4b.z, r4b.w};

    int cc[8];
#pragma unroll
    for (int k = 0; k < 8; k++) cc[k] = __ldg(&g_cnt[rr[k] * Nn + dd[k]]);

    float4 ww[8];
#pragma unroll
    for (int k = 0; k < 8; k++)
        ww[k] = *(const float4*)(W1 + (rr[k] * Nn + ss[k]) * Hh + q * 4);

    float nn[8];
#pragma unroll
    for (int k = 0; k < 8; k++) nn[k] = 1.0f / fmaxf((float)cc[k], 1.0f);

    if (q == 0) {
        *(float4*)(g_enorm + e0)     = make_float4(nn[0], nn[1], nn[2], nn[3]);
        *(float4*)(g_enorm + e0 + 4) = make_float4(nn[4], nn[5], nn[6], nn[7]);
    }
#pragma unroll
    for (int k = 0; k < 8; k++) {
        float4 v = make_float4(ww[k].x * nn[k], ww[k].y * nn[k],
                               ww[k].z * nn[k], ww[k].w * nn[k]);
        red_add_v4(&g_h1[dd[k] * Hh + q * 4], v);
    }
}

// ---------------------------------------------------------------------------
// Fused k_T (register-weight GEMM, single balanced wave):
//   h = relu(agg + root1 + b1)                (staged ~21.6KB shared per block)
//   T[n][r][l] = sum_h h[n,h] * W2[r,h,l]     (w column = 32 regs, via shared)
//   out[n,l]   = (h @ root2)[l] + b2[l]       (base for layer2 REDs)
// Grid = 296 = 2 blocks x 148 SMs, one balanced wave.
// ---------------------------------------------------------------------------
__global__ void __launch_bounds__(512, 2)
k_T(const float* __restrict__ W2, const float* __restrict__ root1,
    const float* __restrict__ b1, const float* __restrict__ root2,
    const float* __restrict__ b2, float* __restrict__ out) {
    __shared__ float4 sH[NT * 8];        // 169 nodes x 32 h = 21.6KB
    __shared__ float  sW2[Rr * Hh * Ll]; // 16KB
    __shared__ float  sR[Hh * Ll];       // 1KB

    int tid = threadIdx.x;
    int n0 = blockIdx.x * NT;            // first node of this block

    for (int i = tid; i < Rr * Hh * Ll; i += 512) sW2[i] = W2[i];
    for (int i = tid; i < Hh * Ll; i += 512) sR[i] = root2[i];

    // Stage relu(agg + root1 + b1) for NT nodes (coalesced float4 loads)
    int base4 = n0 * 8;                  // float4 index into [n][h] arrays
    for (int idx4 = tid; idx4 < NT * 8; idx4 += 512) {
        int g4 = base4 + idx4;
        float4 hv = make_float4(0.f, 0.f, 0.f, 0.f);
        if (g4 < (Nn * Hh) / 4) {
            float4 av = ((const float4*)g_h1)[g4];
            float4 rv = ((const float4*)root1)[g4];
            int h0 = (idx4 & 7) * 4;
            hv.x = fmaxf(av.x + rv.x + __ldg(b1 + h0 + 0), 0.0f);
            hv.y = fmaxf(av.y + rv.y + __ldg(b1 + h0 + 1), 0.0f);
            hv.z = fmaxf(av.z + rv.z + __ldg(b1 + h0 + 2), 0.0f);
            hv.w = fmaxf(av.w + rv.w + __ldg(b1 + h0 + 3), 0.0f);
        }
        sH[idx4] = hv;
    }
    __syncthreads();

    // W2 column into registers: thread owns (r, l); conflict-free LDS
    int rl = tid & 127;                  // r*8 + l
    int r  = rl >> 3;
    int l  = rl & 7;
    int grp = tid >> 7;                  // 4 node-groups
    float w[Hh];
#pragma unroll
    for (int hh = 0; hh < Hh; hh++)
        w[hh] = sW2[(r * Hh + hh) * Ll + l];

    // Out-base: NT*8 (node,l) tasks over 512 threads
    for (int task = tid; task < NT * 8; task += 512) {
        int node = task >> 3;
        int lo = task & 7;
        int n = n0 + node;
        if (n < Nn) {
            const float* sHf = (const float*)sH;
            float y = __ldg(b2 + lo);
#pragma unroll
            for (int hh = 0; hh < Hh; hh++)
                y += sHf[node * Hh + hh] * sR[hh * Ll + lo];
            out[n * Ll + lo] = y;
        }
    }

    // Main: group grp handles nodes ni = grp, grp+4, ... (43 per group)
#pragma unroll 4
    for (int i = 0; i < 43; i++) {
        int ni = grp + i * 4;
        if (ni >= NT) break;
        int n = n0 + ni;
        if (n >= Nn) break;
        float a0 = 0.0f, a1 = 0.0f, a2 = 0.0f, a3 = 0.0f;
#pragma unroll
        for (int j = 0; j < 8; j++) {
            float4 h4 = sH[ni * 8 + j];          // broadcast LDS.128
            a0 += h4.x * w[j * 4 + 0];
            a1 += h4.y * w[j * 4 + 1];
            a2 += h4.z * w[j * 4 + 2];
            a3 += h4.w * w[j * 4 + 3];
        }
        g_T[n * (Rr * Ll) + rl] = (a0 + a1) + (a2 + a3);
    }
}

// ---------------------------------------------------------------------------
// Layer 2 edge pass: 2 threads per edge (half-row each), 8 edges per thread.
//   out[dst, half*4..] += enorm[e] * T[src][r][half*4..]
// ---------------------------------------------------------------------------
__global__ void k_layer2(const int* __restrict__ src, const int* __restrict__ dst,
                         const int* __restrict__ et, float* __restrict__ out) {
    int g = blockIdx.x * blockDim.x + threadIdx.x;
    int oct = g >> 1;
    int half = g & 1;
    if (oct >= Ee / 8) return;
    int e0 = oct * 8;

    int4 sa = *(const int4*)(src + e0);
    int4 sb = *(const int4*)(src + e0 + 4);
    int4 da = *(const int4*)(dst + e0);
    int4 db = *(const int4*)(dst + e0 + 4);
    int4 ra = *(const int4*)(et + e0);
    int4 rb = *(const int4*)(et + e0 + 4);
    float4 na = *(const float4*)(g_enorm + e0);
    float4 nb = *(const float4*)(g_enorm + e0 + 4);
    int ss[8] = {sa.x, sa.y, sa.z, sa.w, sb.x, sb.y, sb.z, sb.w};
    int dd[8] = {da.x, da.y, da.z, da.w, db.x, db.y, db.z, db.w};
    int rr[8] = {ra.x, ra.y, ra.z, ra.w, rb.x, rb.y, rb.z, rb.w};
    float nn[8] = {na.x, na.y, na.z, na.w, nb.x, nb.y, nb.z, nb.w};

    float4 tv[8];
#pragma unroll
    for (int k = 0; k < 8; k++) {
        tv[k] = *(const float4*)(g_T + (ss[k] * Rr + rr[k]) * Ll + half * 4);
    }
#pragma unroll
    for (int k = 0; k < 8; k++) {
        float4 v = make_float4(tv[k].x * nn[k], tv[k].y * nn[k],
                               tv[k].z * nn[k], tv[k].w * nn[k]);
        red_add_v4(&out[dd[k] * Ll + half * 4], v);
    }
}

// ---------------------------------------------------------------------------
// Final: out = sigmoid(out), elementwise (MUFU exp)
// ---------------------------------------------------------------------------
__global__ void k_final(float* __restrict__ out) {
    int i = blockIdx.x * blockDim.x + threadIdx.x;
    if (i >= (Nn * Ll) / 4) return;
    float4 v = ((const float4*)out)[i];
    v.x = 1.0f / (1.0f + __expf(-v.x));
    v.y = 1.0f / (1.0f + __expf(-v.y));
    v.z = 1.0f / (1.0f + __expf(-v.z));
    v.w = 1.0f / (1.0f + __expf(-v.w));
    ((float4*)out)[i] = v;
}

// ---------------------------------------------------------------------------
extern "C" void kernel_launch(void* const* d_in, const int* in_sizes, int n_in,
                              void* d_out, int out_size) {
    const int* ei    = (const int*)d_in[0];    // edge_index [2, E]
    const int* et    = (const int*)d_in[1];    // edge_type  [E]
    const float* W1  = (const float*)d_in[2];  // [R, N, H]
    const float* rt1 = (const float*)d_in[3];  // [N, H]
    const float* b1  = (const float*)d_in[4];  // [H]
    const float* W2  = (const float*)d_in[5];  // [R, H, L]
    const float* rt2 = (const float*)d_in[6];  // [H, L]
    const float* b2  = (const float*)d_in[7];  // [L]
    float* out = (float*)d_out;                // [N, L]

    const int* src = ei;
    const int* dst = ei + Ee;

    k_zero<<<1024, 256>>>();
    k_count<<<(Ee / 8 + 255) / 256, 256>>>(et, dst);
    k_layer1<<<(Ee / 8) * 8 / 256, 256>>>(src, dst, et, W1);     // 8 thr/edge, 8 edges/thr
    k_T<<<KT_BLOCKS, 512>>>(W2, rt1, b1, rt2, b2, out);          // 1 balanced wave
    k_layer2<<<((Ee / 8) * 2 + 255) / 256, 256>>>(src, dst, et, out); // 2 thr/edge, 8 edges/thr
    k_final<<<((Nn * Ll) / 4 + 255) / 256, 256>>>(out);
}